// round 14
// baseline (speedup 1.0000x reference)
#include <cuda_runtime.h>
#include <cstdint>

#define NSEQ 8
#define QLEN 128
#define NQH 32
#define NKVH 8
#define GQA 4
#define HD 128
#define BLKSZ 16
#define MAXBLK 128
#define LTOT 2048
#define NSEG 4
#define TILEC 32

#define NCT 64
#define NTHREADS 512

// word strides
#define QW 68     // Q/K rows: 136 bf16 = 272B = 17*16B
#define VW 36     // V rows: 72 bf16 = 144B = 9*16B

#define OFF_QH 0
#define OFF_QL (OFF_QH + 256*QW)
#define OFF_KH (OFF_QL + 256*QW)
#define OFF_KL (OFF_KH + NCT*QW)
#define OFF_VH (OFF_KL + NCT*QW)
#define OFF_VL (OFF_VH + 128*VW)
#define SMEM_U32 (OFF_VL + 128*VW)
#define SMEM_BYTES (SMEM_U32*4)

static __device__ __forceinline__ void mma_bf16(float c[4], const uint32_t a[4],
                                                uint32_t b0, uint32_t b1) {
    asm volatile(
        "mma.sync.aligned.m16n8k16.row.col.f32.bf16.bf16.f32 "
        "{%0,%1,%2,%3}, {%4,%5,%6,%7}, {%8,%9}, {%0,%1,%2,%3};"
        : "+f"(c[0]), "+f"(c[1]), "+f"(c[2]), "+f"(c[3])
        : "r"(a[0]), "r"(a[1]), "r"(a[2]), "r"(a[3]), "r"(b0), "r"(b1));
}

static __device__ __forceinline__ void ldsm4(uint32_t& r0, uint32_t& r1,
                                             uint32_t& r2, uint32_t& r3, uint32_t addr) {
    asm volatile("ldmatrix.sync.aligned.m8n8.x4.shared.b16 {%0,%1,%2,%3}, [%4];"
        : "=r"(r0), "=r"(r1), "=r"(r2), "=r"(r3) : "r"(addr));
}

static __device__ __forceinline__ uint32_t smem_u32p(const void* p) {
    uint32_t a;
    asm("{ .reg .u64 t; cvta.to.shared.u64 t, %1; cvt.u32.u64 %0, t; }" : "=r"(a) : "l"(p));
    return a;
}

static __device__ __forceinline__ uint32_t pkbf2(float x0, float x1) {
    uint32_t r;
    asm("cvt.rn.bf16x2.f32 %0, %1, %2;" : "=r"(r) : "f"(x1), "f"(x0));
    return r;
}
static __device__ __forceinline__ void split2(float x0, float x1,
                                              uint32_t& hp, uint32_t& lp) {
    hp = pkbf2(x0, x1);
    float h0 = __uint_as_float(hp << 16);
    float h1 = __uint_as_float(hp & 0xffff0000u);
    lp = pkbf2(x0 - h0, x1 - h1);
}
static __device__ __forceinline__ float tanhapx(float x) {
    float r;
    asm("tanh.approx.f32 %0, %1;" : "=f"(r) : "f"(x));
    return r;
}

__global__ void __launch_bounds__(NTHREADS, 1)
paged_seg_attn_big(const float* __restrict__ q,
                   const float* __restrict__ kc,
                   const float* __restrict__ vc,
                   const int*   __restrict__ bt,
                   const int*   __restrict__ seqlens,
                   const float* __restrict__ scale_p,
                   const float* __restrict__ softcap_p,
                   float*       __restrict__ out)
{
    extern __shared__ uint32_t smw[];
    const uint32_t smb = smem_u32p(smw);
    uint32_t* Qh = smw + OFF_QH;
    uint32_t* Ql = smw + OFF_QL;
    uint32_t* Kh = smw + OFF_KH;
    uint32_t* Kl = smw + OFF_KL;
    uint32_t* Vh = smw + OFF_VH;
    uint32_t* Vl = smw + OFF_VL;

    const int seg = blockIdx.x;
    const int gp  = blockIdx.y;      // g-pair
    const int z   = blockIdx.z;
    const int s   = z >> 3;
    const int kv  = z & 7;

    const int tid  = threadIdx.x;
    const int w    = tid >> 5;       // 0..15: CTA q rows w*16..+15 (of 256)
    const int lane = tid & 31;
    const int gid  = lane >> 2;
    const int tig  = lane & 3;
    const int qb   = w * 16;

    const int h    = kv * GQA + gp * 2 + (qb >> 7);   // warp's head
    const int qrow = qb & 127;                        // query row within head

    const float scale = *scale_p;
    const float cap   = *softcap_p;
    const float scoef = (cap > 0.f) ? (scale / cap) : 0.f;

    const int seq_len   = seqlens[s];
    const int ctx       = seq_len - QLEN;
    const int span      = ((seq_len + NSEG * TILEC - 1) / (NSEG * TILEC)) * TILEC;
    const int seg_start = seg * span;
    const int seg_end   = min(seg_start + span, LTOT);

    const int kmax0 = ctx + qrow + gid;
    const int kmax1 = kmax0 + 8;

    const int* btrow = bt + s * MAXBLK;

    // ldmatrix bases (bytes)
    const int lrow16 = lane & 15;
    const int lhi    = lane >> 4;
    const uint32_t aQh = smb + OFF_QH*4 + (qb + lrow16)*272 + lhi*16;
    const uint32_t aQl = smb + OFF_QL*4 + (qb + lrow16)*272 + lhi*16;
    const int brow = (lane & 7) + ((lane >> 4) & 1) * 8;
    const int bkof = ((lane >> 3) & 1) * 8;
    const uint32_t bKh = smb + OFF_KH*4 + brow*272 + bkof*2;
    const uint32_t bKl = smb + OFF_KL*4 + brow*272 + bkof*2;
    const uint32_t bVh = smb + OFF_VH*4 + brow*144 + bkof*2;
    const uint32_t bVl = smb + OFF_VL*4 + brow*144 + bkof*2;

    // ---- stage Q: 256 rows (2 heads x 128 q), [row][d], hi/lo ----
    #pragma unroll
    for (int it = 0; it < 16; it++) {
        int i  = tid + it * NTHREADS;        // 0..8191
        int r  = i >> 5;                     // 0..255
        int d4 = (i & 31) * 4;
        int hh = kv * GQA + gp * 2 + (r >> 7);
        const float* src = q + ((size_t)(s * QLEN + (r & 127)) * NQH + hh) * HD + d4;
        float4 v = *(const float4*)src;
        uint32_t h01, l01, h23, l23;
        split2(v.x, v.y, h01, l01);
        split2(v.z, v.w, h23, l23);
        int o2 = r * QW + (d4 >> 1);
        *(uint2*)(Qh + o2) = make_uint2(h01, h23);
        *(uint2*)(Ql + o2) = make_uint2(l01, l23);
    }

    float o[16][4];
    #pragma unroll
    for (int a = 0; a < 16; a++)
        #pragma unroll
        for (int b = 0; b < 4; b++) o[a][b] = 0.f;

    float pmax0 = 0.f, pmax1 = 0.f;

    for (int base = seg_start; base < seg_end; base += NCT) {
        __syncthreads();

        // ---- stage K: [tok][d], lanes sweep d-pairs; 64 toks ----
        #pragma unroll
        for (int it = 0; it < 2; it++) {
            int i  = tid + it * NTHREADS;    // 0..1023
            int d2 = i & 63;
            int t0 = (i >> 6) * 4;           // 0..60
            int pb = btrow[(base >> 4) + (t0 >> 4)];
            const float* kb0 = kc + (((size_t)pb * NKVH + kv) * HD + 2*d2) * BLKSZ + (t0 & 15);
            float4 va = *(const float4*)(kb0);
            float4 vb = *(const float4*)(kb0 + BLKSZ);
            float ea[4] = {va.x, va.y, va.z, va.w};
            float eb[4] = {vb.x, vb.y, vb.z, vb.w};
            #pragma unroll
            for (int j = 0; j < 4; j++) {
                uint32_t hp, lp;
                split2(ea[j], eb[j], hp, lp);
                Kh[(t0 + j) * QW + d2] = hp;
                Kl[(t0 + j) * QW + d2] = lp;
            }
        }
        // ---- stage V: [d][tok]; 128 d x 64 toks ----
        #pragma unroll
        for (int it = 0; it < 2; it++) {
            int i  = tid + it * NTHREADS;    // 0..1023
            int d  = i >> 3;                 // 0..127
            int th = i & 7;                  // 8-tok group
            int pb = btrow[(base >> 4) + (th >> 1)];
            const float* vb0 = vc + (((size_t)pb * NKVH + kv) * HD + d) * BLKSZ + ((th & 1) * 8);
            float4 va = *(const float4*)(vb0);
            float4 vb = *(const float4*)(vb0 + 4);
            uint4 hv, lv;
            split2(va.x, va.y, hv.x, lv.x);
            split2(va.z, va.w, hv.y, lv.y);
            split2(vb.x, vb.y, hv.z, lv.z);
            split2(vb.z, vb.w, hv.w, lv.w);
            *(uint4*)(Vh + d * VW + th * 4) = hv;
            *(uint4*)(Vl + d * VW + th * 4) = lv;
        }
        __syncthreads();

        // ---- QK: 16q x 64tok per warp, 8 k16 steps, 3-term ----
        float sacc[8][4];
        #pragma unroll
        for (int a = 0; a < 8; a++)
            #pragma unroll
            for (int b = 0; b < 4; b++) sacc[a][b] = 0.f;

        #pragma unroll
        for (int ks = 0; ks < 8; ks++) {
            uint32_t ah[4], al[4];
            ldsm4(ah[0], ah[1], ah[2], ah[3], aQh + ks * 32);
            ldsm4(al[0], al[1], al[2], al[3], aQl + ks * 32);
            #pragma unroll
            for (int ntp = 0; ntp < 4; ntp++) {
                uint32_t bh0A, bh1A, bh0B, bh1B, bl0A, bl1A, bl0B, bl1B;
                ldsm4(bh0A, bh1A, bh0B, bh1B, bKh + ntp * (16*272) + ks * 32);
                ldsm4(bl0A, bl1A, bl0B, bl1B, bKl + ntp * (16*272) + ks * 32);
                mma_bf16(sacc[2*ntp  ], ah, bh0A, bh1A);
                mma_bf16(sacc[2*ntp  ], al, bh0A, bh1A);
                mma_bf16(sacc[2*ntp  ], ah, bl0A, bl1A);
                mma_bf16(sacc[2*ntp+1], ah, bh0B, bh1B);
                mma_bf16(sacc[2*ntp+1], al, bh0B, bh1B);
                mma_bf16(sacc[2*ntp+1], ah, bl0B, bl1B);
            }
        }

        // ---- per k16-step j: softcap + mask + p = exp(v - cap), then PV ----
        #pragma unroll
        for (int j = 0; j < 4; j++) {
            uint32_t pah[4], pal[4];
            #pragma unroll
            for (int t = 0; t < 2; t++) {
                int nt = 2 * j + t;
                float pe[4];
                #pragma unroll
                for (int e = 0; e < 4; e++) {
                    int tpos = base + nt * 8 + 2 * tig + (e & 1);
                    int kmax = (e < 2) ? kmax0 : kmax1;
                    float raw = sacc[nt][e];
                    float v   = cap * tanhapx(raw * scoef);   // softcapped score
                    float p   = __expf(v - cap);
                    bool ok   = (tpos <= kmax) && (tpos < seg_end);
                    p = ok ? p : 0.f;
                    if (e < 2) pmax0 = fmaxf(pmax0, p); else pmax1 = fmaxf(pmax1, p);
                    pe[e] = p;
                }
                split2(pe[0], pe[1], pah[2*t    ], pal[2*t    ]);
                split2(pe[2], pe[3], pah[2*t + 1], pal[2*t + 1]);
            }
            #pragma unroll
            for (int ntp = 0; ntp < 8; ntp++) {
                uint32_t bh0A, bh1A, bh0B, bh1B, bl0A, bl1A, bl0B, bl1B;
                ldsm4(bh0A, bh1A, bh0B, bh1B, bVh + ntp * (16*144) + j * 32);
                ldsm4(bl0A, bl1A, bl0B, bl1B, bVl + ntp * (16*144) + j * 32);
                mma_bf16(o[2*ntp  ], pah, bh0A, bh1A);
                mma_bf16(o[2*ntp  ], pal, bh0A, bh1A);
                mma_bf16(o[2*ntp  ], pah, bl0A, bl1A);
                mma_bf16(o[2*ntp+1], pah, bh0B, bh1B);
                mma_bf16(o[2*ntp+1], pal, bh0B, bh1B);
                mma_bf16(o[2*ntp+1], pah, bl0B, bl1B);
            }
        }
    }

    // ---- epilogue: warp-local pmax reduce, scale, store ----
    #pragma unroll
    for (int off = 1; off < 4; off <<= 1) {
        pmax0 = fmaxf(pmax0, __shfl_xor_sync(0xffffffffu, pmax0, off));
        pmax1 = fmaxf(pmax1, __shfl_xor_sync(0xffffffffu, pmax1, off));
    }
    const float f0 = (pmax0 > 0.f) ? (1.0f / pmax0) : 0.f;
    const float f1 = (pmax1 > 0.f) ? (1.0f / pmax1) : 0.f;

    const int trow0 = s * QLEN + qrow + gid;
    float* o0 = out + (((size_t)trow0       * NQH + h) * NSEG + seg) * (size_t)HD;
    float* o1 = out + (((size_t)(trow0 + 8) * NQH + h) * NSEG + seg) * (size_t)HD;
    #pragma unroll
    for (int nt = 0; nt < 16; nt++) {
        int c = nt * 8 + 2 * tig;
        *(float2*)(o0 + c) = make_float2(o[nt][0] * f0, o[nt][1] * f0);
        *(float2*)(o1 + c) = make_float2(o[nt][2] * f1, o[nt][3] * f1);
    }
}

extern "C" void kernel_launch(void* const* d_in, const int* in_sizes, int n_in,
                              void* d_out, int out_size) {
    const float* q   = (const float*)d_in[0];
    const float* kc  = (const float*)d_in[1];
    const float* vc  = (const float*)d_in[2];
    const int*   bt  = (const int*)d_in[3];
    const int*   sl  = (const int*)d_in[4];
    const float* sc  = (const float*)d_in[6];
    const float* cap = (const float*)d_in[9];
    float* out = (float*)d_out;

    static int init_done = 0;
    if (!init_done) {
        cudaFuncSetAttribute(paged_seg_attn_big,
                             cudaFuncAttributeMaxDynamicSharedMemorySize, SMEM_BYTES);
        init_done = 1;
    }
    dim3 grid(NSEG, 2, NSEQ * NKVH);
    paged_seg_attn_big<<<grid, NTHREADS, SMEM_BYTES>>>(q, kc, vc, bt, sl, sc, cap, out);
}

// round 15
// speedup vs baseline: 1.1153x; 1.1153x over previous
#include <cuda_runtime.h>
#include <cstdint>

#define NSEQ 8
#define QLEN 128
#define NQH 32
#define NKVH 8
#define GQA 4
#define HD 128
#define BLKSZ 16
#define MAXBLK 128
#define LTOT 2048
#define NSEG 4
#define TILEC 32

#define NCT 32
#define NTHREADS 256

#define PLANE 16777216            // NSEQ*MAXBLK*NKVH*HD*BLKSZ elements

// word (u32) layout of dynamic smem
#define QW 68                      // Q rows: 272B
#define KROWW 20                   // K/V rows: 80B (64B data + 16B pad)
#define OFF_QH 0
#define OFF_QL (OFF_QH + 128*QW)
#define OFF_KH (OFF_QL + 128*QW)
#define OFF_KL (OFF_KH + 128*KROWW)
#define OFF_VH (OFF_KL + 128*KROWW)
#define OFF_VL (OFF_VH + 128*KROWW)
#define SMEM_U32 (OFF_VL + 128*KROWW)
#define SMEM_BYTES (SMEM_U32*4)

__device__ __align__(16) unsigned short g_Kh[PLANE];
__device__ __align__(16) unsigned short g_Kl[PLANE];
__device__ __align__(16) unsigned short g_Vh[PLANE];
__device__ __align__(16) unsigned short g_Vl[PLANE];

static __device__ __forceinline__ void mma_bf16(float c[4], const uint32_t a[4],
                                                uint32_t b0, uint32_t b1) {
    asm volatile(
        "mma.sync.aligned.m16n8k16.row.col.f32.bf16.bf16.f32 "
        "{%0,%1,%2,%3}, {%4,%5,%6,%7}, {%8,%9}, {%0,%1,%2,%3};"
        : "+f"(c[0]), "+f"(c[1]), "+f"(c[2]), "+f"(c[3])
        : "r"(a[0]), "r"(a[1]), "r"(a[2]), "r"(a[3]), "r"(b0), "r"(b1));
}
static __device__ __forceinline__ void ldsm4(uint32_t& r0, uint32_t& r1,
                                             uint32_t& r2, uint32_t& r3, uint32_t addr) {
    asm volatile("ldmatrix.sync.aligned.m8n8.x4.shared.b16 {%0,%1,%2,%3}, [%4];"
        : "=r"(r0), "=r"(r1), "=r"(r2), "=r"(r3) : "r"(addr));
}
static __device__ __forceinline__ void ldsm4t(uint32_t& r0, uint32_t& r1,
                                              uint32_t& r2, uint32_t& r3, uint32_t addr) {
    asm volatile("ldmatrix.sync.aligned.m8n8.x4.trans.shared.b16 {%0,%1,%2,%3}, [%4];"
        : "=r"(r0), "=r"(r1), "=r"(r2), "=r"(r3) : "r"(addr));
}
static __device__ __forceinline__ uint32_t smem_u32p(const void* p) {
    uint32_t a;
    asm("{ .reg .u64 t; cvta.to.shared.u64 t, %1; cvt.u32.u64 %0, t; }" : "=r"(a) : "l"(p));
    return a;
}
static __device__ __forceinline__ uint32_t pkbf2(float x0, float x1) {
    uint32_t r;
    asm("cvt.rn.bf16x2.f32 %0, %1, %2;" : "=r"(r) : "f"(x1), "f"(x0));
    return r;
}
static __device__ __forceinline__ void split2(float x0, float x1,
                                              uint32_t& hp, uint32_t& lp) {
    hp = pkbf2(x0, x1);
    float h0 = __uint_as_float(hp << 16);
    float h1 = __uint_as_float(hp & 0xffff0000u);
    lp = pkbf2(x0 - h0, x1 - h1);
}
static __device__ __forceinline__ float tanhapx(float x) {
    float r;
    asm("tanh.approx.f32 %0, %1;" : "=f"(r) : "f"(x));
    return r;
}
static __device__ __forceinline__ void cpasync16(uint32_t dst, const void* src) {
    asm volatile("cp.async.cg.shared.global [%0], [%1], 16;"
        :: "r"(dst), "l"(__cvta_generic_to_global(src)) : "memory");
}
#define CP_COMMIT() asm volatile("cp.async.commit_group;" ::: "memory")
#define CP_WAIT_ALL() asm volatile("cp.async.wait_group 0;" ::: "memory")

// ---------------- pre-pass: fp32 cache -> bf16 hi/lo planes ----------------
__global__ void __launch_bounds__(256, 4)
convert_cache(const float* __restrict__ kc, const float* __restrict__ vc) {
    size_t i8 = ((size_t)blockIdx.x * 256 + threadIdx.x) * 8;
    float4 a = *(const float4*)(kc + i8);
    float4 b = *(const float4*)(kc + i8 + 4);
    uint4 hi, lo;
    split2(a.x, a.y, hi.x, lo.x);
    split2(a.z, a.w, hi.y, lo.y);
    split2(b.x, b.y, hi.z, lo.z);
    split2(b.z, b.w, hi.w, lo.w);
    *(uint4*)(g_Kh + i8) = hi;
    *(uint4*)(g_Kl + i8) = lo;
    a = *(const float4*)(vc + i8);
    b = *(const float4*)(vc + i8 + 4);
    split2(a.x, a.y, hi.x, lo.x);
    split2(a.z, a.w, hi.y, lo.y);
    split2(b.x, b.y, hi.z, lo.z);
    split2(b.z, b.w, hi.w, lo.w);
    *(uint4*)(g_Vh + i8) = hi;
    *(uint4*)(g_Vl + i8) = lo;
}

// ---------------- main kernel ----------------
__global__ void __launch_bounds__(NTHREADS, 2)
paged_seg_attn_cp(const float* __restrict__ q,
                  const int*   __restrict__ bt,
                  const int*   __restrict__ seqlens,
                  const float* __restrict__ scale_p,
                  const float* __restrict__ softcap_p,
                  float*       __restrict__ out)
{
    extern __shared__ uint32_t smw[];
    const uint32_t smb = smem_u32p(smw);
    uint32_t* Qh = smw + OFF_QH;
    uint32_t* Ql = smw + OFF_QL;

    const int bx  = blockIdx.x;      // seg*2 + qhalf
    const int seg = bx >> 1;
    const int qh  = bx & 1;
    const int gp  = blockIdx.y;
    const int z   = blockIdx.z;
    const int s   = z >> 3;
    const int kv  = z & 7;

    const int tid  = threadIdx.x;
    const int w    = tid >> 5;       // 0..7: CTA q rows w*16..+15 (of 128)
    const int lane = tid & 31;
    const int gid  = lane >> 2;
    const int tig  = lane & 3;
    const int qb   = w * 16;

    const int h    = kv * GQA + gp * 2 + (qb >> 6);
    const int qrow = qb & 63;

    const float scale = *scale_p;
    const float cap   = *softcap_p;
    const float scoef = (cap > 0.f) ? (scale / cap) : 0.f;

    const int seq_len   = seqlens[s];
    const int ctx       = seq_len - QLEN;
    const int span      = ((seq_len + NSEG * TILEC - 1) / (NSEG * TILEC)) * TILEC;
    const int seg_start = seg * span;
    const int seg_end   = min(seg_start + span, LTOT);

    const int kmax0 = ctx + qh * 64 + qrow + gid;
    const int kmax1 = kmax0 + 8;

    const int* btrow = bt + s * MAXBLK;

    // ldmatrix per-thread bases (bytes)
    const int lrow16 = lane & 15;
    const int lhi    = lane >> 4;
    const uint32_t aQh = smb + OFF_QH*4 + (qb + lrow16)*272 + lhi*16;
    const uint32_t aQl = smb + OFF_QL*4 + (qb + lrow16)*272 + lhi*16;
    // K trans B-frag: rows = d (k-dim), 80B stride
    const uint32_t bKt = smb + OFF_KH*4 + lrow16*80 + lhi*16;
    // V non-trans B-frag: rows = d (n-dim)
    const uint32_t bVt = smb + OFF_VH*4 +
        ((lane & 7) + ((lane >> 4) & 1) * 8)*80 + ((lane >> 3) & 1)*16;
    const uint32_t KPL = (OFF_KL - OFF_KH) * 4;   // plane offset bytes
    const uint32_t VPL = (OFF_VL - OFF_VH) * 4;

    // ---- stage Q: 128 rows, [row][d], hi/lo (once, regular stores) ----
    #pragma unroll
    for (int it = 0; it < 16; it++) {
        int i  = tid + it * NTHREADS;        // 0..4095
        int r  = i >> 5;                     // 0..127
        int d4 = (i & 31) * 4;
        int hh = kv * GQA + gp * 2 + (r >> 6);
        const float* src = q + ((size_t)(s * QLEN + qh * 64 + (r & 63)) * NQH + hh) * HD + d4;
        float4 v = *(const float4*)src;
        uint32_t h01, l01, h23, l23;
        split2(v.x, v.y, h01, l01);
        split2(v.z, v.w, h23, l23);
        int o2 = r * QW + (d4 >> 1);
        *(uint2*)(Qh + o2) = make_uint2(h01, h23);
        *(uint2*)(Ql + o2) = make_uint2(l01, l23);
    }

    // staging helpers (4 cp.asyncs each for K or V per thread)
    const size_t kvbase = (size_t)kv * (HD * BLKSZ);
    // chunk staging index decode (i in 0..1023): half=i&1, d=(i>>1)&127, blk=(i>>8)&1, plane=(i>>9)&1
    const int st_half  = tid & 1;
    const int st_d     = (tid >> 1) & 127;

    float o[16][4];
    #pragma unroll
    for (int a = 0; a < 16; a++)
        #pragma unroll
        for (int b = 0; b < 4; b++) o[a][b] = 0.f;

    float pmax0 = 0.f, pmax1 = 0.f;

    // ---- prolog: stage K(chunk 0) ----
    {
        int pb0 = btrow[seg_start >> 4], pb1 = btrow[(seg_start >> 4) + 1];
        #pragma unroll
        for (int it = 0; it < 4; it++) {
            int i = tid + it * NTHREADS;
            int blk = (i >> 8) & 1;
            int plane = (i >> 9) & 1;
            int pb = blk ? pb1 : pb0;
            const unsigned short* sp = (plane ? g_Kl : g_Kh) +
                ((size_t)pb * NKVH * (HD*BLKSZ) + kvbase + st_d * 16 + st_half * 8);
            uint32_t dst = smb + OFF_KH*4 + plane*KPL + st_d*80 + blk*32 + st_half*16;
            cpasync16(dst, sp);
        }
        CP_COMMIT();
    }

    for (int base = seg_start; base < seg_end; base += NCT) {
        CP_WAIT_ALL();
        __syncthreads();                  // K(c) visible; prev PV done

        // ---- stage V(c) (overlaps QK) ----
        {
            int pb0 = btrow[base >> 4], pb1 = btrow[(base >> 4) + 1];
            #pragma unroll
            for (int it = 0; it < 4; it++) {
                int i = tid + it * NTHREADS;
                int blk = (i >> 8) & 1;
                int plane = (i >> 9) & 1;
                int pb = blk ? pb1 : pb0;
                const unsigned short* sp = (plane ? g_Vl : g_Vh) +
                    ((size_t)pb * NKVH * (HD*BLKSZ) + kvbase + st_d * 16 + st_half * 8);
                uint32_t dst = smb + OFF_VH*4 + plane*VPL + st_d*80 + blk*32 + st_half*16;
                cpasync16(dst, sp);
            }
            CP_COMMIT();
        }

        // ---- QK: 16q x 32tok per warp, 8 k16 steps, 3-term, K via trans ldsm ----
        float sacc[4][4];
        #pragma unroll
        for (int a = 0; a < 4; a++)
            #pragma unroll
            for (int b = 0; b < 4; b++) sacc[a][b] = 0.f;

        #pragma unroll
        for (int ks = 0; ks < 8; ks++) {
            uint32_t ah[4], al[4];
            ldsm4(ah[0], ah[1], ah[2], ah[3], aQh + ks * 32);
            ldsm4(al[0], al[1], al[2], al[3], aQl + ks * 32);
            #pragma unroll
            for (int x4 = 0; x4 < 2; x4++) {       // n16 window each
                uint32_t kaddr = bKt + ks * (16*80) + x4 * 32;
                uint32_t bh0, bh1, bh2, bh3, bl0, bl1, bl2, bl3;
                ldsm4t(bh0, bh1, bh2, bh3, kaddr);
                ldsm4t(bl0, bl1, bl2, bl3, kaddr + KPL);
                int n0 = 2 * x4, n1 = 2 * x4 + 1;
                mma_bf16(sacc[n0], ah, bh0, bh1);
                mma_bf16(sacc[n0], al, bh0, bh1);
                mma_bf16(sacc[n0], ah, bl0, bl1);
                mma_bf16(sacc[n1], ah, bh2, bh3);
                mma_bf16(sacc[n1], al, bh2, bh3);
                mma_bf16(sacc[n1], ah, bl2, bl3);
            }
        }

        CP_WAIT_ALL();
        __syncthreads();                  // V(c) visible; QK done (K buffer free)

        // ---- stage K(c+1) (overlaps softmax + PV) ----
        if (base + NCT < seg_end) {
            int nb = (base + NCT) >> 4;
            int pb0 = btrow[nb], pb1 = btrow[nb + 1];
            #pragma unroll
            for (int it = 0; it < 4; it++) {
                int i = tid + it * NTHREADS;
                int blk = (i >> 8) & 1;
                int plane = (i >> 9) & 1;
                int pb = blk ? pb1 : pb0;
                const unsigned short* sp = (plane ? g_Kl : g_Kh) +
                    ((size_t)pb * NKVH * (HD*BLKSZ) + kvbase + st_d * 16 + st_half * 8);
                uint32_t dst = smb + OFF_KH*4 + plane*KPL + st_d*80 + blk*32 + st_half*16;
                cpasync16(dst, sp);
            }
            CP_COMMIT();
        }

        // ---- softmax + PV per 16-tok k-step ----
        #pragma unroll
        for (int j = 0; j < 2; j++) {
            uint32_t pah[4], pal[4];
            #pragma unroll
            for (int t = 0; t < 2; t++) {
                int nt = 2 * j + t;
                float pe[4];
                #pragma unroll
                for (int e = 0; e < 4; e++) {
                    int tpos = base + nt * 8 + 2 * tig + (e & 1);
                    int kmax = (e < 2) ? kmax0 : kmax1;
                    float raw = sacc[nt][e];
                    float v   = cap * tanhapx(raw * scoef);
                    float p   = __expf(v - cap);
                    bool ok   = (tpos <= kmax) && (tpos < seg_end);
                    p = ok ? p : 0.f;
                    if (e < 2) pmax0 = fmaxf(pmax0, p); else pmax1 = fmaxf(pmax1, p);
                    pe[e] = p;
                }
                split2(pe[0], pe[1], pah[2*t    ], pal[2*t    ]);
                split2(pe[2], pe[3], pah[2*t + 1], pal[2*t + 1]);
            }
            #pragma unroll
            for (int ntp = 0; ntp < 8; ntp++) {
                uint32_t vaddr = bVt + ntp * (16*80) + j * 32;
                uint32_t bh0, bh1, bh2, bh3, bl0, bl1, bl2, bl3;
                ldsm4(bh0, bh1, bh2, bh3, vaddr);
                ldsm4(bl0, bl1, bl2, bl3, vaddr + VPL);
                mma_bf16(o[2*ntp  ], pah, bh0, bh1);
                mma_bf16(o[2*ntp  ], pal, bh0, bh1);
                mma_bf16(o[2*ntp  ], pah, bl0, bl1);
                mma_bf16(o[2*ntp+1], pah, bh2, bh3);
                mma_bf16(o[2*ntp+1], pal, bh2, bh3);
                mma_bf16(o[2*ntp+1], pah, bl2, bl3);
            }
        }
    }

    // ---- epilogue: warp-local pmax reduce, scale, store ----
    #pragma unroll
    for (int off = 1; off < 4; off <<= 1) {
        pmax0 = fmaxf(pmax0, __shfl_xor_sync(0xffffffffu, pmax0, off));
        pmax1 = fmaxf(pmax1, __shfl_xor_sync(0xffffffffu, pmax1, off));
    }
    const float f0 = (pmax0 > 0.f) ? (1.0f / pmax0) : 0.f;
    const float f1 = (pmax1 > 0.f) ? (1.0f / pmax1) : 0.f;

    const int trow0 = s * QLEN + qh * 64 + qrow + gid;
    float* o0 = out + (((size_t)trow0       * NQH + h) * NSEG + seg) * (size_t)HD;
    float* o1 = out + (((size_t)(trow0 + 8) * NQH + h) * NSEG + seg) * (size_t)HD;
    #pragma unroll
    for (int nt = 0; nt < 16; nt++) {
        int c = nt * 8 + 2 * tig;
        *(float2*)(o0 + c) = make_float2(o[nt][0] * f0, o[nt][1] * f0);
        *(float2*)(o1 + c) = make_float2(o[nt][2] * f1, o[nt][3] * f1);
    }
}

extern "C" void kernel_launch(void* const* d_in, const int* in_sizes, int n_in,
                              void* d_out, int out_size) {
    const float* q   = (const float*)d_in[0];
    const float* kc  = (const float*)d_in[1];
    const float* vc  = (const float*)d_in[2];
    const int*   bt  = (const int*)d_in[3];
    const int*   sl  = (const int*)d_in[4];
    const float* sc  = (const float*)d_in[6];
    const float* cap = (const float*)d_in[9];
    float* out = (float*)d_out;

    static int init_done = 0;
    if (!init_done) {
        cudaFuncSetAttribute(paged_seg_attn_cp,
                             cudaFuncAttributeMaxDynamicSharedMemorySize, SMEM_BYTES);
        init_done = 1;
    }

    convert_cache<<<PLANE / (256 * 8), 256>>>(kc, vc);

    dim3 grid(NSEG * 2, 2, NSEQ * NKVH);
    paged_seg_attn_cp<<<grid, NTHREADS, SMEM_BYTES>>>(q, bt, sl, sc, cap, out);
}

// round 16
// speedup vs baseline: 1.1457x; 1.0272x over previous
#include <cuda_runtime.h>
#include <cstdint>

#define NSEQ 8
#define QLEN 128
#define NQH 32
#define NKVH 8
#define GQA 4
#define HD 128
#define BLKSZ 16
#define MAXBLK 128
#define LTOT 2048
#define NSEG 4
#define TILEC 32

#define NCT 32
#define NTHREADS 256

#define PLANE 16777216            // NSEQ*MAXBLK*NKVH*HD*BLKSZ elements

// word (u32) layout of dynamic smem
#define QW 68                      // Q rows: 272B
#define KROWW 20                   // K/V rows: 80B (64B data + 16B pad)
#define OFF_QH 0
#define OFF_QL (OFF_QH + 128*QW)
#define OFF_KH (OFF_QL + 128*QW)
#define OFF_KL (OFF_KH + 128*KROWW)
#define OFF_VH (OFF_KL + 128*KROWW)
#define OFF_VL (OFF_VH + 128*KROWW)
#define SMEM_U32 (OFF_VL + 128*KROWW)
#define SMEM_BYTES (SMEM_U32*4)

__device__ __align__(16) unsigned short g_Kh[PLANE];
__device__ __align__(16) unsigned short g_Kl[PLANE];
__device__ __align__(16) unsigned short g_Vh[PLANE];
__device__ __align__(16) unsigned short g_Vl[PLANE];

static __device__ __forceinline__ void mma_bf16(float c[4], const uint32_t a[4],
                                                uint32_t b0, uint32_t b1) {
    asm volatile(
        "mma.sync.aligned.m16n8k16.row.col.f32.bf16.bf16.f32 "
        "{%0,%1,%2,%3}, {%4,%5,%6,%7}, {%8,%9}, {%0,%1,%2,%3};"
        : "+f"(c[0]), "+f"(c[1]), "+f"(c[2]), "+f"(c[3])
        : "r"(a[0]), "r"(a[1]), "r"(a[2]), "r"(a[3]), "r"(b0), "r"(b1));
}
static __device__ __forceinline__ void ldsm4(uint32_t& r0, uint32_t& r1,
                                             uint32_t& r2, uint32_t& r3, uint32_t addr) {
    asm volatile("ldmatrix.sync.aligned.m8n8.x4.shared.b16 {%0,%1,%2,%3}, [%4];"
        : "=r"(r0), "=r"(r1), "=r"(r2), "=r"(r3) : "r"(addr));
}
static __device__ __forceinline__ void ldsm4t(uint32_t& r0, uint32_t& r1,
                                              uint32_t& r2, uint32_t& r3, uint32_t addr) {
    asm volatile("ldmatrix.sync.aligned.m8n8.x4.trans.shared.b16 {%0,%1,%2,%3}, [%4];"
        : "=r"(r0), "=r"(r1), "=r"(r2), "=r"(r3) : "r"(addr));
}
static __device__ __forceinline__ uint32_t smem_u32p(const void* p) {
    uint32_t a;
    asm("{ .reg .u64 t; cvta.to.shared.u64 t, %1; cvt.u32.u64 %0, t; }" : "=r"(a) : "l"(p));
    return a;
}
static __device__ __forceinline__ uint32_t pkbf2(float x0, float x1) {
    uint32_t r;
    asm("cvt.rn.bf16x2.f32 %0, %1, %2;" : "=r"(r) : "f"(x1), "f"(x0));
    return r;
}
static __device__ __forceinline__ void split2(float x0, float x1,
                                              uint32_t& hp, uint32_t& lp) {
    hp = pkbf2(x0, x1);
    float h0 = __uint_as_float(hp << 16);
    float h1 = __uint_as_float(hp & 0xffff0000u);
    lp = pkbf2(x0 - h0, x1 - h1);
}
static __device__ __forceinline__ float tanhapx(float x) {
    float r;
    asm("tanh.approx.f32 %0, %1;" : "=f"(r) : "f"(x));
    return r;
}
static __device__ __forceinline__ void cpasync16(uint32_t dst, const void* src) {
    asm volatile("cp.async.cg.shared.global [%0], [%1], 16;"
        :: "r"(dst), "l"(__cvta_generic_to_global(src)) : "memory");
}
#define CP_COMMIT() asm volatile("cp.async.commit_group;" ::: "memory")
#define CP_WAIT_ALL() asm volatile("cp.async.wait_group 0;" ::: "memory")

// ---------------- pre-pass: fp32 cache -> bf16 hi/lo planes ----------------
__global__ void __launch_bounds__(256, 4)
convert_cache(const float* __restrict__ kc, const float* __restrict__ vc) {
    size_t i8 = ((size_t)blockIdx.x * 256 + threadIdx.x) * 8;
    float4 a = *(const float4*)(kc + i8);
    float4 b = *(const float4*)(kc + i8 + 4);
    uint4 hi, lo;
    split2(a.x, a.y, hi.x, lo.x);
    split2(a.z, a.w, hi.y, lo.y);
    split2(b.x, b.y, hi.z, lo.z);
    split2(b.z, b.w, hi.w, lo.w);
    *(uint4*)(g_Kh + i8) = hi;
    *(uint4*)(g_Kl + i8) = lo;
    a = *(const float4*)(vc + i8);
    b = *(const float4*)(vc + i8 + 4);
    split2(a.x, a.y, hi.x, lo.x);
    split2(a.z, a.w, hi.y, lo.y);
    split2(b.x, b.y, hi.z, lo.z);
    split2(b.z, b.w, hi.w, lo.w);
    *(uint4*)(g_Vh + i8) = hi;
    *(uint4*)(g_Vl + i8) = lo;
}

// ---------------- main kernel ----------------
__global__ void __launch_bounds__(NTHREADS, 2)
paged_seg_attn_cp2(const float* __restrict__ q,
                   const int*   __restrict__ bt,
                   const int*   __restrict__ seqlens,
                   const float* __restrict__ scale_p,
                   const float* __restrict__ softcap_p,
                   float*       __restrict__ out)
{
    extern __shared__ uint32_t smw[];
    const uint32_t smb = smem_u32p(smw);
    uint32_t* Qh = smw + OFF_QH;
    uint32_t* Ql = smw + OFF_QL;

    const int bx  = blockIdx.x;      // seg*2 + qhalf
    const int seg = bx >> 1;
    const int qh  = bx & 1;
    const int gp  = blockIdx.y;
    const int z   = blockIdx.z;
    const int s   = z >> 3;
    const int kv  = z & 7;

    const int tid  = threadIdx.x;
    const int w    = tid >> 5;       // 0..7: CTA q rows w*16..+15 (of 128)
    const int lane = tid & 31;
    const int gid  = lane >> 2;
    const int tig  = lane & 3;
    const int qb   = w * 16;

    const int h    = kv * GQA + gp * 2 + (qb >> 6);
    const int qrow = qb & 63;

    const float scale = *scale_p;
    const float cap   = *softcap_p;
    const float scoef = (cap > 0.f) ? (scale / cap) : 0.f;

    const int seq_len   = seqlens[s];
    const int ctx       = seq_len - QLEN;
    const int span      = ((seq_len + NSEG * TILEC - 1) / (NSEG * TILEC)) * TILEC;
    const int seg_start = seg * span;
    const int seg_end   = min(seg_start + span, LTOT);

    const int kmax0 = ctx + qh * 64 + qrow + gid;
    const int kmax1 = kmax0 + 8;
    const int kmin_warp = ctx + qh * 64 + qrow;        // min kmax over warp lanes
    const int kmax_cta  = ctx + qh * 64 + 63;          // max kmax over CTA

    const int* btrow = bt + s * MAXBLK;

    // ldmatrix per-thread bases (bytes)
    const int lrow16 = lane & 15;
    const int lhi    = lane >> 4;
    const uint32_t aQh = smb + OFF_QH*4 + (qb + lrow16)*272 + lhi*16;
    const uint32_t aQl = smb + OFF_QL*4 + (qb + lrow16)*272 + lhi*16;
    const uint32_t bKt = smb + OFF_KH*4 + lrow16*80 + lhi*16;
    const uint32_t bVt = smb + OFF_VH*4 +
        ((lane & 7) + ((lane >> 4) & 1) * 8)*80 + ((lane >> 3) & 1)*16;
    const uint32_t KPL = (OFF_KL - OFF_KH) * 4;
    const uint32_t VPL = (OFF_VL - OFF_VH) * 4;

    // ---- stage Q: 128 rows, [row][d], hi/lo ----
    #pragma unroll
    for (int it = 0; it < 16; it++) {
        int i  = tid + it * NTHREADS;
        int r  = i >> 5;
        int d4 = (i & 31) * 4;
        int hh = kv * GQA + gp * 2 + (r >> 6);
        const float* src = q + ((size_t)(s * QLEN + qh * 64 + (r & 63)) * NQH + hh) * HD + d4;
        float4 v = *(const float4*)src;
        uint32_t h01, l01, h23, l23;
        split2(v.x, v.y, h01, l01);
        split2(v.z, v.w, h23, l23);
        int o2 = r * QW + (d4 >> 1);
        *(uint2*)(Qh + o2) = make_uint2(h01, h23);
        *(uint2*)(Ql + o2) = make_uint2(l01, l23);
    }

    const size_t kvbase = (size_t)kv * (HD * BLKSZ);
    const int st_half  = tid & 1;
    const int st_d     = (tid >> 1) & 127;

    float o[16][4];
    #pragma unroll
    for (int a = 0; a < 16; a++)
        #pragma unroll
        for (int b = 0; b < 4; b++) o[a][b] = 0.f;

    float pmax0 = 0.f, pmax1 = 0.f;

    // ---- prolog: stage K(chunk 0) ----
    {
        int pb0 = btrow[seg_start >> 4], pb1 = btrow[(seg_start >> 4) + 1];
        #pragma unroll
        for (int it = 0; it < 4; it++) {
            int i = tid + it * NTHREADS;
            int blk = (i >> 8) & 1;
            int plane = (i >> 9) & 1;
            int pb = blk ? pb1 : pb0;
            const unsigned short* sp = (plane ? g_Kl : g_Kh) +
                ((size_t)pb * NKVH * (HD*BLKSZ) + kvbase + st_d * 16 + st_half * 8);
            uint32_t dst = smb + OFF_KH*4 + plane*KPL + st_d*80 + blk*32 + st_half*16;
            cpasync16(dst, sp);
        }
        CP_COMMIT();
    }

    for (int base = seg_start; base < seg_end; base += NCT) {
        if (base > kmax_cta) break;       // CTA-uniform causal early exit

        CP_WAIT_ALL();
        __syncthreads();                  // K(c) visible; prev PV done

        // ---- stage V(c) ----
        {
            int pb0 = btrow[base >> 4], pb1 = btrow[(base >> 4) + 1];
            #pragma unroll
            for (int it = 0; it < 4; it++) {
                int i = tid + it * NTHREADS;
                int blk = (i >> 8) & 1;
                int plane = (i >> 9) & 1;
                int pb = blk ? pb1 : pb0;
                const unsigned short* sp = (plane ? g_Vl : g_Vh) +
                    ((size_t)pb * NKVH * (HD*BLKSZ) + kvbase + st_d * 16 + st_half * 8);
                uint32_t dst = smb + OFF_VH*4 + plane*VPL + st_d*80 + blk*32 + st_half*16;
                cpasync16(dst, sp);
            }
            CP_COMMIT();
        }

        // ---- QK: 16q x 32tok per warp, interleaved 2-chain MMAs ----
        float sacc[4][4];
        #pragma unroll
        for (int a = 0; a < 4; a++)
            #pragma unroll
            for (int b = 0; b < 4; b++) sacc[a][b] = 0.f;

        #pragma unroll
        for (int ks = 0; ks < 8; ks++) {
            uint32_t ah[4], al[4];
            ldsm4(ah[0], ah[1], ah[2], ah[3], aQh + ks * 32);
            ldsm4(al[0], al[1], al[2], al[3], aQl + ks * 32);
            #pragma unroll
            for (int x4 = 0; x4 < 2; x4++) {
                uint32_t kaddr = bKt + ks * (16*80) + x4 * 32;
                uint32_t bh0, bh1, bh2, bh3, bl0, bl1, bl2, bl3;
                ldsm4t(bh0, bh1, bh2, bh3, kaddr);
                ldsm4t(bl0, bl1, bl2, bl3, kaddr + KPL);
                int n0 = 2 * x4, n1 = 2 * x4 + 1;
                // two independent accumulator chains, alternating
                mma_bf16(sacc[n0], ah, bh0, bh1);
                mma_bf16(sacc[n1], ah, bh2, bh3);
                mma_bf16(sacc[n0], al, bh0, bh1);
                mma_bf16(sacc[n1], al, bh2, bh3);
                mma_bf16(sacc[n0], ah, bl0, bl1);
                mma_bf16(sacc[n1], ah, bl2, bl3);
            }
        }

        CP_WAIT_ALL();
        __syncthreads();                  // V(c) visible; QK done

        // ---- stage K(c+1) ----
        if (base + NCT < seg_end && base + NCT <= kmax_cta) {
            int nb = (base + NCT) >> 4;
            int pb0 = btrow[nb], pb1 = btrow[nb + 1];
            #pragma unroll
            for (int it = 0; it < 4; it++) {
                int i = tid + it * NTHREADS;
                int blk = (i >> 8) & 1;
                int plane = (i >> 9) & 1;
                int pb = blk ? pb1 : pb0;
                const unsigned short* sp = (plane ? g_Kl : g_Kh) +
                    ((size_t)pb * NKVH * (HD*BLKSZ) + kvbase + st_d * 16 + st_half * 8);
                uint32_t dst = smb + OFF_KH*4 + plane*KPL + st_d*80 + blk*32 + st_half*16;
                cpasync16(dst, sp);
            }
            CP_COMMIT();
        }

        // ---- softmax + PV per 16-tok k-step ----
        const bool safe = (base + NCT - 1 <= kmin_warp) && (base + NCT <= seg_end);
        #pragma unroll
        for (int j = 0; j < 2; j++) {
            uint32_t pah[4], pal[4];
            if (safe) {
                #pragma unroll
                for (int t = 0; t < 2; t++) {
                    int nt = 2 * j + t;
                    float pe[4];
                    #pragma unroll
                    for (int e = 0; e < 4; e++) {
                        float v = cap * tanhapx(sacc[nt][e] * scoef);
                        float p = __expf(v - cap);
                        if (e < 2) pmax0 = fmaxf(pmax0, p); else pmax1 = fmaxf(pmax1, p);
                        pe[e] = p;
                    }
                    split2(pe[0], pe[1], pah[2*t    ], pal[2*t    ]);
                    split2(pe[2], pe[3], pah[2*t + 1], pal[2*t + 1]);
                }
            } else {
                #pragma unroll
                for (int t = 0; t < 2; t++) {
                    int nt = 2 * j + t;
                    float pe[4];
                    #pragma unroll
                    for (int e = 0; e < 4; e++) {
                        int tpos = base + nt * 8 + 2 * tig + (e & 1);
                        int kmax = (e < 2) ? kmax0 : kmax1;
                        float v = cap * tanhapx(sacc[nt][e] * scoef);
                        float p = __expf(v - cap);
                        bool ok = (tpos <= kmax) && (tpos < seg_end);
                        p = ok ? p : 0.f;
                        if (e < 2) pmax0 = fmaxf(pmax0, p); else pmax1 = fmaxf(pmax1, p);
                        pe[e] = p;
                    }
                    split2(pe[0], pe[1], pah[2*t    ], pal[2*t    ]);
                    split2(pe[2], pe[3], pah[2*t + 1], pal[2*t + 1]);
                }
            }
            #pragma unroll
            for (int np = 0; np < 4; np++) {     // pairs of ntp: 2 B-tiles, 4 chains
                int ntp0 = 2 * np, ntp1 = 2 * np + 1;
                uint32_t va0 = bVt + ntp0 * (16*80) + j * 32;
                uint32_t va1 = bVt + ntp1 * (16*80) + j * 32;
                uint32_t b0h0, b0h1, b0h2, b0h3, b0l0, b0l1, b0l2, b0l3;
                uint32_t b1h0, b1h1, b1h2, b1h3, b1l0, b1l1, b1l2, b1l3;
                ldsm4(b0h0, b0h1, b0h2, b0h3, va0);
                ldsm4(b0l0, b0l1, b0l2, b0l3, va0 + VPL);
                ldsm4(b1h0, b1h1, b1h2, b1h3, va1);
                ldsm4(b1l0, b1l1, b1l2, b1l3, va1 + VPL);
                // 4 interleaved chains
                mma_bf16(o[2*ntp0  ], pah, b0h0, b0h1);
                mma_bf16(o[2*ntp0+1], pah, b0h2, b0h3);
                mma_bf16(o[2*ntp1  ], pah, b1h0, b1h1);
                mma_bf16(o[2*ntp1+1], pah, b1h2, b1h3);
                mma_bf16(o[2*ntp0  ], pal, b0h0, b0h1);
                mma_bf16(o[2*ntp0+1], pal, b0h2, b0h3);
                mma_bf16(o[2*ntp1  ], pal, b1h0, b1h1);
                mma_bf16(o[2*ntp1+1], pal, b1h2, b1h3);
                mma_bf16(o[2*ntp0  ], pah, b0l0, b0l1);
                mma_bf16(o[2*ntp0+1], pah, b0l2, b0l3);
                mma_bf16(o[2*ntp1  ], pah, b1l0, b1l1);
                mma_bf16(o[2*ntp1+1], pah, b1l2, b1l3);
            }
        }
    }

    CP_WAIT_ALL();   // retire any orphaned prefetch after early exit

    // ---- epilogue: warp-local pmax reduce, scale, store ----
    #pragma unroll
    for (int off = 1; off < 4; off <<= 1) {
        pmax0 = fmaxf(pmax0, __shfl_xor_sync(0xffffffffu, pmax0, off));
        pmax1 = fmaxf(pmax1, __shfl_xor_sync(0xffffffffu, pmax1, off));
    }
    const float f0 = (pmax0 > 0.f) ? (1.0f / pmax0) : 0.f;
    const float f1 = (pmax1 > 0.f) ? (1.0f / pmax1) : 0.f;

    const int trow0 = s * QLEN + qh * 64 + qrow + gid;
    float* o0 = out + (((size_t)trow0       * NQH + h) * NSEG + seg) * (size_t)HD;
    float* o1 = out + (((size_t)(trow0 + 8) * NQH + h) * NSEG + seg) * (size_t)HD;
    #pragma unroll
    for (int nt = 0; nt < 16; nt++) {
        int c = nt * 8 + 2 * tig;
        *(float2*)(o0 + c) = make_float2(o[nt][0] * f0, o[nt][1] * f0);
        *(float2*)(o1 + c) = make_float2(o[nt][2] * f1, o[nt][3] * f1);
    }
}

extern "C" void kernel_launch(void* const* d_in, const int* in_sizes, int n_in,
                              void* d_out, int out_size) {
    const float* q   = (const float*)d_in[0];
    const float* kc  = (const float*)d_in[1];
    const float* vc  = (const float*)d_in[2];
    const int*   bt  = (const int*)d_in[3];
    const int*   sl  = (const int*)d_in[4];
    const float* sc  = (const float*)d_in[6];
    const float* cap = (const float*)d_in[9];
    float* out = (float*)d_out;

    static int init_done = 0;
    if (!init_done) {
        cudaFuncSetAttribute(paged_seg_attn_cp2,
                             cudaFuncAttributeMaxDynamicSharedMemorySize, SMEM_BYTES);
        init_done = 1;
    }

    convert_cache<<<PLANE / (256 * 8), 256>>>(kc, vc);

    dim3 grid(NSEG * 2, 2, NSEQ * NKVH);
    paged_seg_attn_cp2<<<grid, NTHREADS, SMEM_BYTES>>>(q, bt, sl, sc, cap, out);
}